// round 12
// baseline (speedup 1.0000x reference)
#include <cuda_runtime.h>

// Problem constants (fixed-shape problem)
#define NB      32
#define NSITES  65536
#define NNGB    13
#define DIM     3
#define NG      48
#define KDIM    (NG * DIM)             // 144
#define NPREP   16
#define ROWS_PER_PREP (KDIM / NPREP)   // 9

typedef unsigned long long ull;

// Scratch (device-global: allocation-free rule)
__device__ __align__(16) float g_InT[NSITES * NB];   // 8 MB, site-major transpose
__device__ float g_Wpart[NPREP][DIM * NNGB];
__device__ float g_Wmean[DIM * NNGB];

// packed f32x2 FMA: d = a*b + d elementwise on float pairs in one b64 reg
__device__ __forceinline__ void ffma2(ull& d, ull a, ull b) {
    asm("fma.rn.f32x2 %0, %1, %2, %0;" : "+l"(d) : "l"(a), "l"(b));
}

// ---------------------------------------------------------------------------
// Kernel 1: partial Wmean. 16 blocks x 320 threads; block p handles gdiags
// rows [9p, 9p+9). B[k][j] = wtVC[k%3][GnnPerms[k/3][j]].
// ---------------------------------------------------------------------------
__global__ __launch_bounds__(320)
void prep_kernel(const float* __restrict__ wtVC,
                 const float* __restrict__ gdiags,
                 const int*   __restrict__ GnnPerms) {
    __shared__ float B[KDIM][NNGB];
    __shared__ float sW[DIM * NNGB];
    int tid = threadIdx.x;

    if (tid < DIM * NNGB) sW[tid] = 0.f;
    for (int i = tid; i < KDIM * NNGB; i += 320) {
        int k = i / NNGB, j = i % NNGB;
        B[k][j] = wtVC[(k % 3) * NNGB + GnnPerms[(k / 3) * NNGB + j]];
    }
    __syncthreads();

    int w = tid >> 5, lane = tid & 31;
    if (w < ROWS_PER_PREP) {
        int r = blockIdx.x * ROWS_PER_PREP + w;
        float acc[NNGB];
        #pragma unroll
        for (int j = 0; j < NNGB; j++) acc[j] = 0.f;
        for (int k = lane; k < KDIM; k += 32) {            // coalesced row read
            float gv = gdiags[r * KDIM + k];
            #pragma unroll
            for (int j = 0; j < NNGB; j++) acc[j] += gv * B[k][j];
        }
        #pragma unroll
        for (int j = 0; j < NNGB; j++) {
            #pragma unroll
            for (int off = 16; off > 0; off >>= 1)
                acc[j] += __shfl_xor_sync(0xffffffffu, acc[j], off);
        }
        if (lane == 0) {
            int d = r % 3;
            #pragma unroll
            for (int j = 0; j < NNGB; j++)
                atomicAdd(&sW[d * NNGB + j], acc[j]);
        }
    }
    __syncthreads();
    if (tid < DIM * NNGB) g_Wpart[blockIdx.x][tid] = sW[tid];
}

// ---------------------------------------------------------------------------
// Kernel 2: transpose In (NB x NSITES) -> g_InT (NSITES x NB, fp32).
// Block 0 additionally reduces Wmean partials (prep done: stream order).
// ---------------------------------------------------------------------------
__global__ void transpose_kernel(const float* __restrict__ In) {
    __shared__ float tile[32][33];
    int tx = threadIdx.x, ty = threadIdx.y;
    int tid = ty * 32 + tx;

    if (blockIdx.x == 0 && tid < DIM * NNGB) {
        float s = 0.f;
        #pragma unroll
        for (int p = 0; p < NPREP; p++) s += g_Wpart[p][tid];
        g_Wmean[tid] = s * (1.0f / (float)NG);
    }

    int s0 = blockIdx.x * 32;
    tile[ty][tx] = In[ty * NSITES + s0 + tx];          // coalesced read
    __syncthreads();
    g_InT[(s0 + ty) * NB + tx] = tile[tx][ty];         // coalesced write
}

// ---------------------------------------------------------------------------
// Kernel 3: gather + contraction. r9 skeleton (MLP-batched 13x LDG.128,
// STG.128 epilogue) with fma.rn.f32x2 packed math:
//   - 6 NAMED scalar ull accumulators (no asm-constrained arrays -> no
//     local-memory demotion, the r6 pathology)
//   - weights pre-packed {w,w} as ull in smem, LDS.64 broadcast
//   - FFMA instr per thread: 312 -> 156 FFMA2
// occ cap 2 -> 128-reg budget: 52 (v) + 12 (acc) + 13 (idx) + misc ~ 92.
// ---------------------------------------------------------------------------
__global__ __launch_bounds__(256, 2)
void conv_kernel(const int* __restrict__ NNsites, float* __restrict__ out) {
    __shared__ ull   Wm2[DIM * NNGB];     // packed {w,w}
    __shared__ int   sidx[NNGB][32];
    __shared__ float sout[DIM * 1064];    // d*1064 + b*33 + si : conflict-free

    int tid = threadIdx.x;
    int s0  = blockIdx.x * 32;

    if (tid < DIM * NNGB) {
        unsigned int wb = __float_as_uint(g_Wmean[tid]);
        Wm2[tid] = ((ull)wb << 32) | wb;
    }
    for (int i = tid; i < NNGB * 32; i += 256) {
        int j = i >> 5, si = i & 31;
        sidx[j][si] = NNsites[j * NSITES + s0 + si];   // coalesced
    }
    __syncthreads();

    int w    = tid >> 5;
    int l    = tid & 31;
    int site = (w << 2) + (l >> 3);   // 0..31
    int c    = l & 7;                 // 16B chunk -> batches 4c..4c+3

    const ulonglong2* __restrict__ InT2 = (const ulonglong2*)g_InT;

    // 1) all indices (broadcast LDS), 2) all 13 LDG.128 back-to-back, 3) math.
    int idx[NNGB];
    #pragma unroll
    for (int j = 0; j < NNGB; j++) idx[j] = sidx[j][site];

    ulonglong2 v[NNGB];                // .x = batches (4c,4c+1), .y = (4c+2,4c+3)
    #pragma unroll
    for (int j = 0; j < NNGB; j++) v[j] = __ldg(&InT2[idx[j] * 8 + c]);

    ull a00 = 0ull, a01 = 0ull;        // dim0: pair(4c,4c+1), pair(4c+2,4c+3)
    ull a10 = 0ull, a11 = 0ull;        // dim1
    ull a20 = 0ull, a21 = 0ull;        // dim2  (bit pattern 0 == (0.f,0.f))

    #pragma unroll
    for (int j = 0; j < NNGB; j++) {
        ull w0 = Wm2[j], w1 = Wm2[NNGB + j], w2 = Wm2[2 * NNGB + j];
        ffma2(a00, v[j].x, w0); ffma2(a01, v[j].y, w0);
        ffma2(a10, v[j].x, w1); ffma2(a11, v[j].y, w1);
        ffma2(a20, v[j].x, w2); ffma2(a21, v[j].y, w2);
    }

    // Stage: word = d*1064 + b*33 + site; bank = (8d + b + site) mod 32.
    // Per slot: b = 4c+k, site = 4w+r -> 4c+r distinct over 32 lanes. ✓
    int b0 = c << 2;
    float2 p;
    p = *reinterpret_cast<float2*>(&a00);
    sout[0 * 1064 + (b0 + 0) * 33 + site] = p.x;
    sout[0 * 1064 + (b0 + 1) * 33 + site] = p.y;
    p = *reinterpret_cast<float2*>(&a01);
    sout[0 * 1064 + (b0 + 2) * 33 + site] = p.x;
    sout[0 * 1064 + (b0 + 3) * 33 + site] = p.y;
    p = *reinterpret_cast<float2*>(&a10);
    sout[1 * 1064 + (b0 + 0) * 33 + site] = p.x;
    sout[1 * 1064 + (b0 + 1) * 33 + site] = p.y;
    p = *reinterpret_cast<float2*>(&a11);
    sout[1 * 1064 + (b0 + 2) * 33 + site] = p.x;
    sout[1 * 1064 + (b0 + 3) * 33 + site] = p.y;
    p = *reinterpret_cast<float2*>(&a20);
    sout[2 * 1064 + (b0 + 0) * 33 + site] = p.x;
    sout[2 * 1064 + (b0 + 1) * 33 + site] = p.y;
    p = *reinterpret_cast<float2*>(&a21);
    sout[2 * 1064 + (b0 + 2) * 33 + site] = p.x;
    sout[2 * 1064 + (b0 + 3) * 33 + site] = p.y;
    __syncthreads();

    // 768 float4 = 3072 floats; 3 STG.128 per thread, fully coalesced.
    #pragma unroll
    for (int k = 0; k < 3; k++) {
        int f4  = tid + (k << 8);    // 0..767
        int pj  = f4 & 7;            // float4 chunk within (b,d) row
        int row = f4 >> 3;           // 0..95 = b*3+d
        int d   = row % 3;
        int b   = row / 3;
        int si  = pj << 2;
        float4 o;
        o.x = sout[d * 1064 + b * 33 + si];
        o.y = sout[d * 1064 + b * 33 + si + 1];
        o.z = sout[d * 1064 + b * 33 + si + 2];
        o.w = sout[d * 1064 + b * 33 + si + 3];
        ((float4*)(out + row * NSITES + s0))[pj] = o;
    }
}

// ---------------------------------------------------------------------------
// Launch: In, wtVC, gdiags, GnnPerms, NNsites (metadata order)
// ---------------------------------------------------------------------------
extern "C" void kernel_launch(void* const* d_in, const int* in_sizes, int n_in,
                              void* d_out, int out_size) {
    const float* In       = (const float*)d_in[0];
    const float* wtVC     = (const float*)d_in[1];
    const float* gdiags   = (const float*)d_in[2];
    const int*   GnnPerms = (const int*)  d_in[3];
    const int*   NNsites  = (const int*)  d_in[4];
    float*       out      = (float*)d_out;

    prep_kernel<<<NPREP, 320>>>(wtVC, gdiags, GnnPerms);

    dim3 tblk(32, 32);
    transpose_kernel<<<NSITES / 32, tblk>>>(In);

    conv_kernel<<<NSITES / 32, 256>>>(NNsites, out);
}

// round 13
// speedup vs baseline: 1.1498x; 1.1498x over previous
#include <cuda_runtime.h>

// Problem constants (fixed-shape problem)
#define NB      32
#define NSITES  65536
#define NNGB    13
#define DIM     3
#define NG      48
#define KDIM    (NG * DIM)             // 144
#define NPREP   16
#define TSITES  128                    // sites per transpose tile
#define NTRANS  (NSITES / TSITES)      // 512 transpose blocks

// Scratch (device-global: allocation-free rule)
__device__ __align__(16) float g_InT[NSITES * NB];   // 8 MB, site-major transpose
__device__ float g_Wpart[NPREP][DIM * NNGB];

// ---------------------------------------------------------------------------
// Kernel T: fused transpose + Wmean partials. 512+16 blocks x 256 threads.
//  - blocks [0, NTRANS): transpose a 32-batch x 128-site tile of In into
//    g_InT (site-major). 16 elts/thread; reads 512B segments, writes 128B rows.
//  - blocks [NTRANS, NTRANS+16): block p computes gdiags rows [9p,9p+9)
//    contribution to Wmean -> g_Wpart[p]. Hidden under the transpose wave.
// Shared memory is a union: transpose needs 16.5KB tile, prep needs 7.6KB.
// ---------------------------------------------------------------------------
#define T_SMEM_BYTES (32 * 129 * 4)    // 16512 >= prep's 7648

__global__ __launch_bounds__(256)
void fused_t_kernel(const float* __restrict__ In,
                    const float* __restrict__ wtVC,
                    const float* __restrict__ gdiags,
                    const int*   __restrict__ GnnPerms) {
    __shared__ __align__(16) unsigned char s_raw[T_SMEM_BYTES];
    int tid = threadIdx.x;

    if (blockIdx.x < NTRANS) {
        float* tile = (float*)s_raw;               // [32][129] padded
        int s0 = blockIdx.x * TSITES;
        // read: 4096 elts; i = tid + 256k -> b = i/128, x = i%128 (coalesced)
        #pragma unroll
        for (int k = 0; k < 16; k++) {
            int i = tid + (k << 8);
            int b = i >> 7, x = i & 127;
            tile[b * 129 + x] = In[b * NSITES + s0 + x];
        }
        __syncthreads();
        // write: i -> sl = i/32, b = i%32 (128B coalesced; LDS banks distinct)
        #pragma unroll
        for (int k = 0; k < 16; k++) {
            int i  = tid + (k << 8);
            int sl = i >> 5, b = i & 31;
            g_InT[(s0 + sl) * NB + b] = tile[b * 129 + sl];
        }
    } else {
        int p = blockIdx.x - NTRANS;
        float* B  = (float*)s_raw;                 // [144][13] = 7488B
        float* sW = (float*)(s_raw + 7488);        // 39 accumulators
        if (tid < DIM * NNGB) sW[tid] = 0.f;
        for (int i = tid; i < KDIM * NNGB; i += 256) {
            int k = i / NNGB, j = i % NNGB;
            B[i] = wtVC[(k % 3) * NNGB + GnnPerms[(k / 3) * NNGB + j]];
        }
        __syncthreads();
        int w = tid >> 5, lane = tid & 31;
        for (int rl = w; rl < 9; rl += 8) {        // 9 rows, 8 warps
            int r = p * 9 + rl;
            float acc[NNGB];
            #pragma unroll
            for (int j = 0; j < NNGB; j++) acc[j] = 0.f;
            for (int k = lane; k < KDIM; k += 32) {   // coalesced row read
                float gv = gdiags[r * KDIM + k];
                #pragma unroll
                for (int j = 0; j < NNGB; j++) acc[j] += gv * B[k * NNGB + j];
            }
            #pragma unroll
            for (int j = 0; j < NNGB; j++) {
                #pragma unroll
                for (int o = 16; o > 0; o >>= 1)
                    acc[j] += __shfl_xor_sync(0xffffffffu, acc[j], o);
            }
            if (lane == 0) {
                int d = r % 3;
                #pragma unroll
                for (int j = 0; j < NNGB; j++)
                    atomicAdd(&sW[d * NNGB + j], acc[j]);
            }
        }
        __syncthreads();
        if (tid < DIM * NNGB) g_Wpart[p][tid] = sW[tid];
    }
}

// ---------------------------------------------------------------------------
// Kernel C: gather + contraction — r9 core VERBATIM (proven 27.4us form):
// MLP-batched 13x LDG.128 into v[13] before any FMA, scalar fp32 FMAs,
// smem-staged STG.128 epilogue, occ 3 (84-reg budget, no spills).
// Only change: Wm reduced from g_Wpart here (prep kernel eliminated).
// ---------------------------------------------------------------------------
__global__ __launch_bounds__(256, 3)
void conv_kernel(const int* __restrict__ NNsites, float* __restrict__ out) {
    __shared__ float Wm[40];
    __shared__ int   sidx[NNGB][32];
    __shared__ float sout[DIM * 1064];    // d*1064 + b*33 + si : conflict-free

    int tid = threadIdx.x;
    int s0  = blockIdx.x * 32;

    if (tid < DIM * NNGB) {
        float s = 0.f;
        #pragma unroll
        for (int p = 0; p < NPREP; p++) s += g_Wpart[p][tid];
        Wm[tid] = s * (1.0f / (float)NG);
    }
    for (int i = tid; i < NNGB * 32; i += 256) {
        int j = i >> 5, si = i & 31;
        sidx[j][si] = NNsites[j * NSITES + s0 + si];   // coalesced
    }
    __syncthreads();

    int w    = tid >> 5;
    int l    = tid & 31;
    int site = (w << 2) + (l >> 3);   // 0..31
    int c    = l & 7;                 // 16B chunk -> batches 4c..4c+3

    const float4* __restrict__ InT4 = (const float4*)g_InT;

    // 1) read all indices (broadcast LDS), 2) issue all 13 gathers, 3) FMA.
    int idx[NNGB];
    #pragma unroll
    for (int j = 0; j < NNGB; j++) idx[j] = sidx[j][site];

    float4 v[NNGB];
    #pragma unroll
    for (int j = 0; j < NNGB; j++) v[j] = __ldg(&InT4[idx[j] * 8 + c]);

    float4 a0 = make_float4(0.f, 0.f, 0.f, 0.f);
    float4 a1 = a0, a2 = a0;
    #pragma unroll
    for (int j = 0; j < NNGB; j++) {
        float w0 = Wm[j], w1 = Wm[NNGB + j], w2 = Wm[2 * NNGB + j];
        a0.x += w0 * v[j].x; a0.y += w0 * v[j].y; a0.z += w0 * v[j].z; a0.w += w0 * v[j].w;
        a1.x += w1 * v[j].x; a1.y += w1 * v[j].y; a1.z += w1 * v[j].z; a1.w += w1 * v[j].w;
        a2.x += w2 * v[j].x; a2.y += w2 * v[j].y; a2.z += w2 * v[j].z; a2.w += w2 * v[j].w;
    }

    // Stage: word = d*1064 + b*33 + site; bank = (8d + b + site) mod 32.
    // Per slot: b = 4c+k, site = 4w+r -> 4c+r distinct over 32 lanes. ✓
    int b0 = c << 2;
    sout[0 * 1064 + (b0 + 0) * 33 + site] = a0.x;
    sout[0 * 1064 + (b0 + 1) * 33 + site] = a0.y;
    sout[0 * 1064 + (b0 + 2) * 33 + site] = a0.z;
    sout[0 * 1064 + (b0 + 3) * 33 + site] = a0.w;
    sout[1 * 1064 + (b0 + 0) * 33 + site] = a1.x;
    sout[1 * 1064 + (b0 + 1) * 33 + site] = a1.y;
    sout[1 * 1064 + (b0 + 2) * 33 + site] = a1.z;
    sout[1 * 1064 + (b0 + 3) * 33 + site] = a1.w;
    sout[2 * 1064 + (b0 + 0) * 33 + site] = a2.x;
    sout[2 * 1064 + (b0 + 1) * 33 + site] = a2.y;
    sout[2 * 1064 + (b0 + 2) * 33 + site] = a2.z;
    sout[2 * 1064 + (b0 + 3) * 33 + site] = a2.w;
    __syncthreads();

    // 768 float4 = 3072 floats; 3 STG.128 per thread, fully coalesced.
    #pragma unroll
    for (int k = 0; k < 3; k++) {
        int f4  = tid + (k << 8);    // 0..767
        int p   = f4 & 7;            // float4 chunk within (b,d) row
        int row = f4 >> 3;           // 0..95 = b*3+d
        int d   = row % 3;
        int b   = row / 3;
        int si  = p << 2;
        float4 o;
        o.x = sout[d * 1064 + b * 33 + si];
        o.y = sout[d * 1064 + b * 33 + si + 1];
        o.z = sout[d * 1064 + b * 33 + si + 2];
        o.w = sout[d * 1064 + b * 33 + si + 3];
        ((float4*)(out + row * NSITES + s0))[p] = o;
    }
}

// ---------------------------------------------------------------------------
// Launch: In, wtVC, gdiags, GnnPerms, NNsites (metadata order). TWO kernels.
// ---------------------------------------------------------------------------
extern "C" void kernel_launch(void* const* d_in, const int* in_sizes, int n_in,
                              void* d_out, int out_size) {
    const float* In       = (const float*)d_in[0];
    const float* wtVC     = (const float*)d_in[1];
    const float* gdiags   = (const float*)d_in[2];
    const int*   GnnPerms = (const int*)  d_in[3];
    const int*   NNsites  = (const int*)  d_in[4];
    float*       out      = (float*)d_out;

    fused_t_kernel<<<NTRANS + NPREP, 256>>>(In, wtVC, gdiags, GnnPerms);

    conv_kernel<<<NSITES / 32, 256>>>(NNsites, out);
}